// round 9
// baseline (speedup 1.0000x reference)
#include <cuda_runtime.h>
#include <cuda_bf16.h>
#include <cstdint>

#define DD    16
#define HH    64
#define WW    64
#define PTOT  (DD*HH*WW)      // 65536
#define C3    21
#define LOG2E 1.4426950408889634f

// scratch: rows 0-63 = q, 64-127 = k, 128-191 = v
__device__ float g_qkv[192 * PTOT];
// x split hi/lo, transposed to [pos][ci] bf16
__device__ __align__(16) __nv_bfloat16 g_xhi[PTOT * 64];
__device__ __align__(16) __nv_bfloat16 g_xlo[PTOT * 64];
// W split hi/lo, [c][ci] bf16 (192 rows x 64) == B col-major for mma
__device__ __align__(16) __nv_bfloat16 g_whi[192 * 64];
__device__ __align__(16) __nv_bfloat16 g_wlo[192 * 64];

__device__ __forceinline__ float ex2(float x) {
    float r;
    asm("ex2.approx.ftz.f32 %0, %1;" : "=f"(r) : "f"(x));
    return r;
}

// ---------------------------------------------------------------------------
// Prep A: split x (fp32 [ci][pos]) into bf16 hi/lo in transposed [pos][ci]
// layout. 64ci x 64pos tile per block, smem transpose (stride 65).
// ---------------------------------------------------------------------------
__global__ void __launch_bounds__(256)
prep_x_kernel(const float* __restrict__ x) {
    __shared__ float tile[64 * 65];
    const int tid = threadIdx.x;
    const int p0  = blockIdx.x * 64;

#pragma unroll
    for (int i = 0; i < 16; i++) {
        int j  = i * 256 + tid;
        int ci = j >> 6, p = j & 63;
        tile[ci * 65 + p] = x[ci * PTOT + p0 + p];
    }
    __syncthreads();
#pragma unroll
    for (int i = 0; i < 16; i++) {
        int j  = i * 256 + tid;
        int p  = j >> 6, ci = j & 63;          // ci fastest -> coalesced writes
        float v = tile[ci * 65 + p];
        __nv_bfloat16 hi = __float2bfloat16(v);
        __nv_bfloat16 lo = __float2bfloat16(v - __bfloat162float(hi));
        g_xhi[(p0 + p) * 64 + ci] = hi;
        g_xlo[(p0 + p) * 64 + ci] = lo;
    }
}

// ---------------------------------------------------------------------------
// Prep B: split W into bf16 hi/lo, rows 0-63=wq, 64-127=wk, 128-191=wv.
// ---------------------------------------------------------------------------
__global__ void prep_w_kernel(const float* __restrict__ wq,
                              const float* __restrict__ wk,
                              const float* __restrict__ wv) {
    int j = blockIdx.x * 256 + threadIdx.x;
    if (j < 192 * 64) {
        int c = j >> 6, ci = j & 63;
        float w;
        if (c < 64)       w = wq[c * 64 + ci];
        else if (c < 128) w = wk[(c - 64) * 64 + ci];
        else              w = wv[(c - 128) * 64 + ci];
        __nv_bfloat16 hi = __float2bfloat16(w);
        __nv_bfloat16 lo = __float2bfloat16(w - __bfloat162float(hi));
        g_whi[j] = hi;
        g_wlo[j] = lo;
    }
}

// ---------------------------------------------------------------------------
// Kernel 1: qkv GEMM via warp-level mma.sync (m16n8k16 bf16, sm_80 baseline).
// Block: 256 thr = 8 warps as 2 pos-warps x 4 chan-warps.
// Block tile: 64 pos x 192 chan. Warp tile: 32 pos x 48 chan (2 m x 6 n).
// 3 passes: Xhi*Whi + Xlo*Whi + Xhi*Wlo (fp32 accum).
// Fragments loaded directly from global as aligned 32-bit words:
//   A row-major [pos][k]:  a0=A[r][kc..+1] a1=A[r+8][kc] a2=A[r][kc+8] a3=A[r+8][kc+8]
//   B col-major (=W[n][k] row-major): b0=W[n][kc..+1] b1=W[n][kc+8]
//   with r,n = lane>>2, kc = (lane&3)*2.
// ---------------------------------------------------------------------------
__device__ __forceinline__ unsigned int ld32(const __nv_bfloat16* p) {
    return *(const unsigned int*)p;
}

__device__ __forceinline__ void mma16816(float* d,
                                         unsigned int a0, unsigned int a1,
                                         unsigned int a2, unsigned int a3,
                                         unsigned int b0, unsigned int b1) {
    asm volatile(
        "mma.sync.aligned.m16n8k16.row.col.f32.bf16.bf16.f32 "
        "{%0,%1,%2,%3}, {%4,%5,%6,%7}, {%8,%9}, {%0,%1,%2,%3};"
        : "+f"(d[0]), "+f"(d[1]), "+f"(d[2]), "+f"(d[3])
        : "r"(a0), "r"(a1), "r"(a2), "r"(a3), "r"(b0), "r"(b1));
}

__global__ void __launch_bounds__(256, 2)
qkv_mma_kernel() {
    const int tid  = threadIdx.x;
    const int lane = tid & 31;
    const int wid  = tid >> 5;
    const int pw   = wid & 1;          // pos-warp 0..1
    const int cw   = wid >> 1;         // chan-warp 0..3

    const int r  = lane >> 2;          // 0..7
    const int kc = (lane & 3) * 2;     // 0,2,4,6

    const int pos0 = blockIdx.x * 64 + pw * 32;   // warp's 32 positions
    const int cb   = cw * 48;                     // warp's 48 channels

    float acc[2][6][4];
#pragma unroll
    for (int m = 0; m < 2; m++)
#pragma unroll
        for (int n = 0; n < 6; n++)
#pragma unroll
            for (int i = 0; i < 4; i++) acc[m][n][i] = 0.f;

    // pass p: A source, B source
    const __nv_bfloat16* Asrc[3] = {g_xhi, g_xlo, g_xhi};
    const __nv_bfloat16* Bsrc[3] = {g_whi, g_whi, g_wlo};

#pragma unroll
    for (int p = 0; p < 3; p++) {
        const __nv_bfloat16* A = Asrc[p] + (size_t)(pos0 + r) * 64 + kc;
        const __nv_bfloat16* B = Bsrc[p] + (size_t)(cb + r) * 64 + kc;

#pragma unroll
        for (int k = 0; k < 4; k++) {          // k-step of 16
            const int ko = k * 16;
            // B fragments for 6 n-tiles
            unsigned int b0[6], b1[6];
#pragma unroll
            for (int n = 0; n < 6; n++) {
                const __nv_bfloat16* Bn = B + n * 8 * 64;
                b0[n] = ld32(Bn + ko);
                b1[n] = ld32(Bn + ko + 8);
            }
#pragma unroll
            for (int m = 0; m < 2; m++) {
                const __nv_bfloat16* Am = A + m * 16 * 64;
                unsigned int a0 = ld32(Am + ko);
                unsigned int a1 = ld32(Am + 8 * 64 + ko);
                unsigned int a2 = ld32(Am + ko + 8);
                unsigned int a3 = ld32(Am + 8 * 64 + ko + 8);
#pragma unroll
                for (int n = 0; n < 6; n++)
                    mma16816(acc[m][n], a0, a1, a2, a3, b0[n], b1[n]);
            }
        }
    }

    // epilogue: d0=(r, c2) d1=(r, c2+1) d2=(r+8, c2) d3=(r+8, c2+1), c2=(lane&3)*2
    const int c2 = (lane & 3) * 2;
#pragma unroll
    for (int m = 0; m < 2; m++) {
#pragma unroll
        for (int n = 0; n < 6; n++) {
            int chan = cb + n * 8 + c2;
            int pos  = pos0 + m * 16 + r;
            g_qkv[(size_t)chan * PTOT + pos]           = acc[m][n][0];
            g_qkv[(size_t)(chan + 1) * PTOT + pos]     = acc[m][n][1];
            g_qkv[(size_t)chan * PTOT + pos + 8]       = acc[m][n][2];
            g_qkv[(size_t)(chan + 1) * PTOT + pos + 8] = acc[m][n][3];
        }
    }
}

// ---------------------------------------------------------------------------
// Kernel 2: windowed softmax attention (unchanged from best round).
// ---------------------------------------------------------------------------
#define ROWLEN 66

template<int A>
__device__ __forceinline__ void tap_loop(const float2* __restrict__ skv,
                                         int ty, int w, float qs,
                                         float qb0, float qb1, float qb2,
                                         float& den, float& num) {
#pragma unroll
    for (int kd = 0; kd < 3; kd++) {
#pragma unroll
        for (int kh = 0; kh < 3; kh++) {
            const float2* row = skv + (kd * 10 + (ty + kh)) * ROWLEN + w;
#pragma unroll
            for (int kw = 0; kw < 3; kw++) {
                float2 kv = row[kw];
                float qb = (A == 0) ? (kd == 0 ? qb0 : kd == 1 ? qb1 : qb2)
                         : (A == 1) ? (kh == 0 ? qb0 : kh == 1 ? qb1 : qb2)
                                    : (kw == 0 ? qb0 : kw == 1 ? qb1 : qb2);
                float e = ex2(fmaf(qs, kv.x, qb));
                den += e;
                num = fmaf(e, kv.y, num);
            }
        }
    }
}

__global__ void __launch_bounds__(512)
attn_kernel(const float* __restrict__ rel_d,
            const float* __restrict__ rel_h,
            const float* __restrict__ rel_w,
            float* __restrict__ out) {
    __shared__ float2 skv[2][3][10][ROWLEN];

    const int w   = threadIdx.x;
    const int ty  = threadIdx.y;
    const int tid = ty * 64 + w;
    const int d   = blockIdx.x >> 3;
    const int h0  = (blockIdx.x & 7) * 8;
    const int c0  = blockIdx.y * 2;

    {
        float2* flat = &skv[0][0][0][0];
        const int TOT = 2 * 3 * 10 * ROWLEN;
        for (int i = tid; i < TOT; i += 512) {
            int ci  = i / (3 * 10 * ROWLEN);
            int r   = i - ci * (3 * 10 * ROWLEN);
            int ndi = r / (10 * ROWLEN);
            int r2  = r - ndi * (10 * ROWLEN);
            int nhi = r2 / ROWLEN;
            int wi  = r2 - nhi * ROWLEN;
            int nd = d + ndi - 1;
            int nh = h0 + nhi - 1;
            int nw = wi - 1;
            float kk = 0.f, vv = 0.f;
            if ((unsigned)nd < (unsigned)DD && (unsigned)nh < (unsigned)HH &&
                (unsigned)nw < (unsigned)WW) {
                int g = (nd << 12) + (nh << 6) + nw;
                kk = g_qkv[(64  + c0 + ci) * PTOT + g];
                vv = g_qkv[(128 + c0 + ci) * PTOT + g];
            }
            flat[i] = make_float2(kk, vv);
        }
    }
    __syncthreads();

    const int h = h0 + ty;
    const int p = (d << 12) + (h << 6) + w;

#pragma unroll
    for (int ci = 0; ci < 2; ci++) {
        const int c = c0 + ci;
        const float q  = g_qkv[c * PTOT + p];
        const float qs = q * LOG2E;

        int axis;
        const float* bp;
        if (c < C3)          { axis = 0; bp = rel_d + c * 3; }
        else if (c < 2 * C3) { axis = 1; bp = rel_h + (c - C3) * 3; }
        else                 { axis = 2; bp = rel_w + (c - 2 * C3) * 3; }
        const float qb0 = qs * bp[0];
        const float qb1 = qs * bp[1];
        const float qb2 = qs * bp[2];

        float den = 0.f, num = 0.f;
        const float2* skv_c = &skv[ci][0][0][0];
        if (axis == 0)      tap_loop<0>(skv_c, ty, w, qs, qb0, qb1, qb2, den, num);
        else if (axis == 1) tap_loop<1>(skv_c, ty, w, qs, qb0, qb1, qb2, den, num);
        else                tap_loop<2>(skv_c, ty, w, qs, qb0, qb1, qb2, den, num);

        out[c * PTOT + p] = __fdividef(num, den);
    }
}

// ---------------------------------------------------------------------------
extern "C" void kernel_launch(void* const* d_in, const int* in_sizes, int n_in,
                              void* d_out, int out_size) {
    const float* x     = (const float*)d_in[0];
    const float* wq    = (const float*)d_in[1];
    const float* wk    = (const float*)d_in[2];
    const float* wv    = (const float*)d_in[3];
    const float* rel_d = (const float*)d_in[4];
    const float* rel_h = (const float*)d_in[5];
    const float* rel_w = (const float*)d_in[6];
    float* out = (float*)d_out;

    prep_w_kernel<<<48, 256>>>(wq, wk, wv);
    prep_x_kernel<<<PTOT / 64, 256>>>(x);

    qkv_mma_kernel<<<PTOT / 64, 256>>>();

    dim3 agrid(DD * (HH / 8), 64 / 2);
    dim3 ablock(WW, 8);
    attn_kernel<<<agrid, ablock>>>(rel_d, rel_h, rel_w, out);
}

// round 10
// speedup vs baseline: 1.1631x; 1.1631x over previous
#include <cuda_runtime.h>
#include <cuda_bf16.h>
#include <cstdint>

#define DD    16
#define HH    64
#define WW    64
#define PTOT  (DD*HH*WW)      // 65536
#define C3    21
#define LOG2E 1.4426950408889634f

// scratch: rows 0-63 = q, 64-127 = k, 128-191 = v
__device__ float g_qkv[192 * PTOT];
// x split hi/lo, transposed to [pos][ci] bf16
__device__ __align__(16) __nv_bfloat16 g_xhi[PTOT * 64];
__device__ __align__(16) __nv_bfloat16 g_xlo[PTOT * 64];
// W split hi/lo, [c][ci] bf16 (192 rows x 64) == B col-major for mma
__device__ __align__(16) __nv_bfloat16 g_whi[192 * 64];
__device__ __align__(16) __nv_bfloat16 g_wlo[192 * 64];

__device__ __forceinline__ float ex2(float x) {
    float r;
    asm("ex2.approx.ftz.f32 %0, %1;" : "=f"(r) : "f"(x));
    return r;
}

// ---------------------------------------------------------------------------
// Prep A: split x (fp32 [ci][pos]) into bf16 hi/lo in transposed [pos][ci].
// ---------------------------------------------------------------------------
__global__ void __launch_bounds__(256)
prep_x_kernel(const float* __restrict__ x) {
    __shared__ float tile[64 * 65];
    const int tid = threadIdx.x;
    const int p0  = blockIdx.x * 64;

#pragma unroll
    for (int i = 0; i < 16; i++) {
        int j  = i * 256 + tid;
        int ci = j >> 6, p = j & 63;
        tile[ci * 65 + p] = x[ci * PTOT + p0 + p];
    }
    __syncthreads();
#pragma unroll
    for (int i = 0; i < 16; i++) {
        int j  = i * 256 + tid;
        int p  = j >> 6, ci = j & 63;
        float v = tile[ci * 65 + p];
        __nv_bfloat16 hi = __float2bfloat16(v);
        __nv_bfloat16 lo = __float2bfloat16(v - __bfloat162float(hi));
        g_xhi[(p0 + p) * 64 + ci] = hi;
        g_xlo[(p0 + p) * 64 + ci] = lo;
    }
}

// ---------------------------------------------------------------------------
// Prep B: split W into bf16 hi/lo, rows 0-63=wq, 64-127=wk, 128-191=wv.
// ---------------------------------------------------------------------------
__global__ void prep_w_kernel(const float* __restrict__ wq,
                              const float* __restrict__ wk,
                              const float* __restrict__ wv) {
    int j = blockIdx.x * 256 + threadIdx.x;
    if (j < 192 * 64) {
        int c = j >> 6, ci = j & 63;
        float w;
        if (c < 64)       w = wq[c * 64 + ci];
        else if (c < 128) w = wk[(c - 64) * 64 + ci];
        else              w = wv[(c - 128) * 64 + ci];
        __nv_bfloat16 hi = __float2bfloat16(w);
        __nv_bfloat16 lo = __float2bfloat16(w - __bfloat162float(hi));
        g_whi[j] = hi;
        g_wlo[j] = lo;
    }
}

// ---------------------------------------------------------------------------
// Kernel 1: qkv GEMM via warp-level mma.sync (m16n8k16 bf16).
// FUSED k-loop: per k-step load ahi/alo/bhi/blo fragments once, issue 3 MMAs
// per (m,n): hi*hi + lo*hi + hi*lo.
// Block 256 thr = 2 pos-warps x 4 chan-warps; warp tile 32 pos x 48 chan.
// ---------------------------------------------------------------------------
__device__ __forceinline__ unsigned int ld32(const __nv_bfloat16* p) {
    return *(const unsigned int*)p;
}

__device__ __forceinline__ void mma16816(float* d,
                                         unsigned int a0, unsigned int a1,
                                         unsigned int a2, unsigned int a3,
                                         unsigned int b0, unsigned int b1) {
    asm volatile(
        "mma.sync.aligned.m16n8k16.row.col.f32.bf16.bf16.f32 "
        "{%0,%1,%2,%3}, {%4,%5,%6,%7}, {%8,%9}, {%0,%1,%2,%3};"
        : "+f"(d[0]), "+f"(d[1]), "+f"(d[2]), "+f"(d[3])
        : "r"(a0), "r"(a1), "r"(a2), "r"(a3), "r"(b0), "r"(b1));
}

__global__ void __launch_bounds__(256, 2)
qkv_mma_kernel() {
    const int tid  = threadIdx.x;
    const int lane = tid & 31;
    const int wid  = tid >> 5;
    const int pw   = wid & 1;
    const int cw   = wid >> 1;

    const int r  = lane >> 2;
    const int kc = (lane & 3) * 2;

    const int pos0 = blockIdx.x * 64 + pw * 32;
    const int cb   = cw * 48;

    float acc[2][6][4];
#pragma unroll
    for (int m = 0; m < 2; m++)
#pragma unroll
        for (int n = 0; n < 6; n++)
#pragma unroll
            for (int i = 0; i < 4; i++) acc[m][n][i] = 0.f;

    const __nv_bfloat16* Axh = g_xhi + (size_t)(pos0 + r) * 64 + kc;
    const __nv_bfloat16* Axl = g_xlo + (size_t)(pos0 + r) * 64 + kc;
    const __nv_bfloat16* Bh  = g_whi + (size_t)(cb + r) * 64 + kc;
    const __nv_bfloat16* Bl  = g_wlo + (size_t)(cb + r) * 64 + kc;

#pragma unroll
    for (int k = 0; k < 4; k++) {
        const int ko = k * 16;
        unsigned int bh0[6], bh1[6], bl0[6], bl1[6];
#pragma unroll
        for (int n = 0; n < 6; n++) {
            const __nv_bfloat16* Bn = Bh + n * 8 * 64;
            bh0[n] = ld32(Bn + ko);
            bh1[n] = ld32(Bn + ko + 8);
            const __nv_bfloat16* Cn = Bl + n * 8 * 64;
            bl0[n] = ld32(Cn + ko);
            bl1[n] = ld32(Cn + ko + 8);
        }
#pragma unroll
        for (int m = 0; m < 2; m++) {
            const __nv_bfloat16* Ah = Axh + m * 16 * 64;
            unsigned int ah0 = ld32(Ah + ko);
            unsigned int ah1 = ld32(Ah + 8 * 64 + ko);
            unsigned int ah2 = ld32(Ah + ko + 8);
            unsigned int ah3 = ld32(Ah + 8 * 64 + ko + 8);
            const __nv_bfloat16* Al = Axl + m * 16 * 64;
            unsigned int al0 = ld32(Al + ko);
            unsigned int al1 = ld32(Al + 8 * 64 + ko);
            unsigned int al2 = ld32(Al + ko + 8);
            unsigned int al3 = ld32(Al + 8 * 64 + ko + 8);
#pragma unroll
            for (int n = 0; n < 6; n++) {
                mma16816(acc[m][n], ah0, ah1, ah2, ah3, bh0[n], bh1[n]);
                mma16816(acc[m][n], al0, al1, al2, al3, bh0[n], bh1[n]);
                mma16816(acc[m][n], ah0, ah1, ah2, ah3, bl0[n], bl1[n]);
            }
        }
    }

    const int c2 = (lane & 3) * 2;
#pragma unroll
    for (int m = 0; m < 2; m++) {
#pragma unroll
        for (int n = 0; n < 6; n++) {
            int chan = cb + n * 8 + c2;
            int pos  = pos0 + m * 16 + r;
            g_qkv[(size_t)chan * PTOT + pos]           = acc[m][n][0];
            g_qkv[(size_t)(chan + 1) * PTOT + pos]     = acc[m][n][1];
            g_qkv[(size_t)chan * PTOT + pos + 8]       = acc[m][n][2];
            g_qkv[(size_t)(chan + 1) * PTOT + pos + 8] = acc[m][n][3];
        }
    }
}

// ---------------------------------------------------------------------------
// Kernel 2: windowed softmax attention, TH=2 h-outputs per thread.
// Block (64 w, 8 ty): 1 channel, 16-h tile. Each thread handles h = hb, hb+1
// (hb = 2*ty) and shares tap loads between the two outputs (rows hb..hb+3).
// smem rows of 66 with always-zero w-halo columns (memset once, no division
// in staging: row = idx>>6, col = idx&63).
// ---------------------------------------------------------------------------
#define RL 66

template<int A>
__device__ __forceinline__ void tap_loop(const float2* __restrict__ skv,
                                         int hb, int w,
                                         float qs0, float qs1,
                                         const float* qb0, const float* qb1,
                                         float& den0, float& num0,
                                         float& den1, float& num1) {
#pragma unroll
    for (int kd = 0; kd < 3; kd++) {
#pragma unroll
        for (int R = 0; R < 4; R++) {
            const float2* row = skv + (kd * 18 + hb + R) * RL + w;
#pragma unroll
            for (int kw = 0; kw < 3; kw++) {
                float2 kv = row[kw];
                if (R <= 2) {
                    const int j = (A == 0) ? kd : (A == 1) ? R : kw;
                    float e = ex2(fmaf(qs0, kv.x, qb0[j]));
                    den0 += e;
                    num0 = fmaf(e, kv.y, num0);
                }
                if (R >= 1) {
                    const int j = (A == 0) ? kd : (A == 1) ? (R - 1) : kw;
                    float e = ex2(fmaf(qs1, kv.x, qb1[j]));
                    den1 += e;
                    num1 = fmaf(e, kv.y, num1);
                }
            }
        }
    }
}

__global__ void __launch_bounds__(512)
attn_kernel(const float* __restrict__ rel_d,
            const float* __restrict__ rel_h,
            const float* __restrict__ rel_w,
            float* __restrict__ out) {
    __shared__ float2 skv[3][18][RL];    // 28512 B

    const int w   = threadIdx.x;
    const int ty  = threadIdx.y;
    const int tid = ty * 64 + w;
    const int d   = blockIdx.x >> 2;
    const int h0  = (blockIdx.x & 3) * 16;
    const int c   = blockIdx.y;

    const float* gk = g_qkv + (size_t)(64  + c) * PTOT;
    const float* gv = g_qkv + (size_t)(128 + c) * PTOT;

    // zero the w-halo columns (cols 0 and 65 of each of the 54 rows)
    if (tid < 108) {
        int row = tid >> 1;
        int col = (tid & 1) * 65;
        (&skv[0][0][0])[row * RL + col] = make_float2(0.f, 0.f);
    }
    // main staging: 54 rows x 64 cols, pow2 decode
    for (int idx = tid; idx < 54 * 64; idx += 512) {
        int row = idx >> 6;            // 0..53
        int col = idx & 63;
        int kd  = row / 18;            // 0..2 (small-const div)
        int R   = row - kd * 18;       // 0..17
        int nd  = d + kd - 1;
        int nh  = h0 + R - 1;
        float kk = 0.f, vv = 0.f;
        if ((unsigned)nd < (unsigned)DD && (unsigned)nh < (unsigned)HH) {
            int g = (nd << 12) + (nh << 6) + col;
            kk = gk[g];
            vv = gv[g];
        }
        skv[kd][R][col + 1] = make_float2(kk, vv);
    }
    __syncthreads();

    const int hb = ty * 2;
    const int p0 = (d << 12) + ((h0 + hb) << 6) + w;
    const float q0 = g_qkv[(size_t)c * PTOT + p0];
    const float q1 = g_qkv[(size_t)c * PTOT + p0 + 64];
    const float qs0 = q0 * LOG2E;
    const float qs1 = q1 * LOG2E;

    int axis;
    const float* bp;
    if (c < C3)          { axis = 0; bp = rel_d + c * 3; }
    else if (c < 2 * C3) { axis = 1; bp = rel_h + (c - C3) * 3; }
    else                 { axis = 2; bp = rel_w + (c - 2 * C3) * 3; }
    float qb0[3], qb1[3];
#pragma unroll
    for (int j = 0; j < 3; j++) {
        float b = bp[j];
        qb0[j] = qs0 * b;
        qb1[j] = qs1 * b;
    }

    float den0 = 0.f, num0 = 0.f, den1 = 0.f, num1 = 0.f;
    const float2* base = &skv[0][0][0];
    if (axis == 0)      tap_loop<0>(base, hb, w, qs0, qs1, qb0, qb1, den0, num0, den1, num1);
    else if (axis == 1) tap_loop<1>(base, hb, w, qs0, qs1, qb0, qb1, den0, num0, den1, num1);
    else                tap_loop<2>(base, hb, w, qs0, qs1, qb0, qb1, den0, num0, den1, num1);

    out[(size_t)c * PTOT + p0]      = __fdividef(num0, den0);
    out[(size_t)c * PTOT + p0 + 64] = __fdividef(num1, den1);
}

// ---------------------------------------------------------------------------
extern "C" void kernel_launch(void* const* d_in, const int* in_sizes, int n_in,
                              void* d_out, int out_size) {
    const float* x     = (const float*)d_in[0];
    const float* wq    = (const float*)d_in[1];
    const float* wk    = (const float*)d_in[2];
    const float* wv    = (const float*)d_in[3];
    const float* rel_d = (const float*)d_in[4];
    const float* rel_h = (const float*)d_in[5];
    const float* rel_w = (const float*)d_in[6];
    float* out = (float*)d_out;

    prep_w_kernel<<<48, 256>>>(wq, wk, wv);
    prep_x_kernel<<<PTOT / 64, 256>>>(x);

    qkv_mma_kernel<<<PTOT / 64, 256>>>();

    dim3 agrid(DD * (HH / 16), 64);    // (64, 64)
    dim3 ablock(WW, 8);
    attn_kernel<<<agrid, ablock>>>(rel_d, rel_h, rel_w, out);
}